// round 5
// baseline (speedup 1.0000x reference)
#include <cuda_runtime.h>

#define FULLMASK 0xffffffffu
#define NEGC (-1000000000.0f)

__device__ __forceinline__ float lse2(float a, float b) {
    float mx = fmaxf(a, b);
    float mn = fminf(a, b);
    return mx + __logf(1.0f + __expf(mn - mx));
}
__device__ __forceinline__ float lse3(float a, float b, float c) {
    float mx = fmaxf(fmaxf(a, b), c);
    return mx + __logf(__expf(a - mx) + __expf(b - mx) + __expf(c - mx));
}

// ---------------------------------------------------------------------------
// Forward pass: one warp per batch. Lane handles columns 4*lane .. 4*lane+3.
// alpha written to `alpha` (native [B,N,M,3] layout, coalesced float4 I/O).
// ---------------------------------------------------------------------------
__global__ void __launch_bounds__(32, 1)
fwd_kernel(const float* __restrict__ theta, const float* __restrict__ Aall,
           float* __restrict__ alpha)
{
    const int b = blockIdx.x;
    const int lane = threadIdx.x;
    const float* Ab = Aall + b * 9;
    const float A00 = Ab[0], A01 = Ab[1], A02 = Ab[2];
    const float A10 = Ab[3], A11 = Ab[4], A12 = Ab[5];
    const float A20 = Ab[6], A21 = Ab[7], A22 = Ab[8];

    const size_t base = (size_t)b * (128 * 128 * 3);
    const float4* thp = reinterpret_cast<const float4*>(theta + base);
    float4* alp = reinterpret_cast<float4*>(alpha + base);
    const int fo = lane * 3;   // float4 offset within a row (row = 96 float4s)

    float pm[4], px[4], py[4];
#pragma unroll
    for (int k = 0; k < 4; k++) { pm[k] = NEGC; px[k] = NEGC; py[k] = NEGC; }

    float4 th0 = thp[fo], th1 = thp[fo + 1], th2v = thp[fo + 2];

    for (int i = 0; i < 128; i++) {
        float4 n0, n1, n2;
        n0 = n1 = n2 = make_float4(0.f, 0.f, 0.f, 0.f);
        if (i < 127) {
            int r2 = (i + 1) * 96 + fo;
            n0 = thp[r2]; n1 = thp[r2 + 1]; n2 = thp[r2 + 2];
        }
        float tf[12];
        *reinterpret_cast<float4*>(&tf[0]) = th0;
        *reinterpret_cast<float4*>(&tf[4]) = th1;
        *reinterpret_cast<float4*>(&tf[8]) = th2v;

        // prev-row values at column-1 (diagonal dependency)
        float pmn = __shfl_up_sync(FULLMASK, pm[3], 1);
        float pxn = __shfl_up_sync(FULLMASK, px[3], 1);
        float pyn = __shfl_up_sync(FULLMASK, py[3], 1);
        if (lane == 0) { pmn = NEGC; pxn = NEGC; pyn = NEGC; }

        float m[4], x[4];
#pragma unroll
        for (int k = 0; k < 4; k++) {
            float dm = k ? pm[k - 1] : pmn;
            float dx = k ? px[k - 1] : pxn;
            float dy = k ? py[k - 1] : pyn;
            float lm = lse3(dm + A00, dx + A10, dy + A20);
            if (i == 0 && lane == 0 && k == 0) lm = 0.0f;   // start cell (0,0,match)
            m[k] = tf[3 * k + 0] + lm;
            x[k] = tf[3 * k + 1] + lse3(pm[k] + A01, px[k] + A11, py[k] + A21);
        }

        // current-row m,x at column-1 (for the y chain's c terms)
        float mnb = __shfl_up_sync(FULLMASK, m[3], 1);
        float xnb = __shfl_up_sync(FULLMASK, x[3], 1);
        if (lane == 0) { mnb = NEGC; xnb = NEGC; }

        float c[4], d[4];
#pragma unroll
        for (int k = 0; k < 4; k++) {
            float mL = k ? m[k - 1] : mnb;
            float xL = k ? x[k - 1] : xnb;
            c[k] = tf[3 * k + 2] + lse2(mL + A02, xL + A12);
            d[k] = tf[3 * k + 2] + A22;
        }

        // local op composition over this lane's 4 columns
        float C = c[0], D = d[0];
#pragma unroll
        for (int k = 1; k < 4; k++) { C = lse2(c[k], d[k] + C); D += d[k]; }
        // Kogge-Stone inclusive warp scan of ops
#pragma unroll
        for (int off = 1; off < 32; off <<= 1) {
            float Cu = __shfl_up_sync(FULLMASK, C, off);
            float Du = __shfl_up_sync(FULLMASK, D, off);
            if (lane >= off) { C = lse2(C, D + Cu); D += Du; }
        }
        // exclusive prefix applied to y_{-1} = NEG
        float Ce = __shfl_up_sync(FULLMASK, C, 1);
        float De = __shfl_up_sync(FULLMASK, D, 1);
        float yin = (lane == 0) ? NEGC : lse2(Ce, De + NEGC);

        float y[4];
#pragma unroll
        for (int k = 0; k < 4; k++) { y[k] = lse2(c[k], d[k] + yin); yin = y[k]; }

        int wo = i * 96 + fo;
        alp[wo]     = make_float4(m[0], x[0], y[0], m[1]);
        alp[wo + 1] = make_float4(x[1], y[1], m[2], x[2]);
        alp[wo + 2] = make_float4(y[2], m[3], x[3], y[3]);

#pragma unroll
        for (int k = 0; k < 4; k++) { pm[k] = m[k]; px[k] = x[k]; py[k] = y[k]; }
        if (i < 127) { th0 = n0; th1 = n1; th2v = n2; }
    }
}

// ---------------------------------------------------------------------------
// Backward + combine: rows N-1..0, right-to-left scan. Lane scan-position
// p = 4*lane + k maps to column jj = 127 - p. Reads alpha from `out`,
// writes out = (alpha + beta) - logZ in place.
// ---------------------------------------------------------------------------
__global__ void __launch_bounds__(32, 1)
bwd_kernel(const float* __restrict__ theta, const float* __restrict__ Aall,
           float* __restrict__ out)
{
    const int b = blockIdx.x;
    const int lane = threadIdx.x;
    const float* Ab = Aall + b * 9;
    const float A00 = Ab[0], A01 = Ab[1], A02 = Ab[2];
    const float A10 = Ab[3], A11 = Ab[4], A12 = Ab[5];
    const float A20 = Ab[6], A21 = Ab[7], A22 = Ab[8];

    const size_t base = (size_t)b * (128 * 128 * 3);
    const float4* thp = reinterpret_cast<const float4*>(theta + base);
    float4* op = reinterpret_cast<float4*>(out + base);

    // logZ from alpha at (N-1, M-1) — read BEFORE any overwrite
    float la0 = out[base + 49149];
    float la1 = out[base + 49150];
    float la2 = out[base + 49151];
    const float logZ = lse3(la0, la1, la2);

    const int fo = (31 - lane) * 3;  // this lane's float4 offset within a row

    float u0p[4], u1p[4];   // prev-row u = beta + theta, states 0 and 1
#pragma unroll
    for (int k = 0; k < 4; k++) { u0p[k] = NEGC; u1p[k] = NEGC; }

    int r0 = 127 * 96 + fo;
    float4 th0 = thp[r0], th1 = thp[r0 + 1], th2v = thp[r0 + 2];
    float4 al0 = op[r0],  al1 = op[r0 + 1],  al2 = op[r0 + 2];

    for (int i = 127; i >= 0; i--) {
        float4 n0, n1, n2, b0v, b1v, b2v;
        n0 = n1 = n2 = b0v = b1v = b2v = make_float4(0.f, 0.f, 0.f, 0.f);
        if (i > 0) {
            int r2 = (i - 1) * 96 + fo;
            n0 = thp[r2]; n1 = thp[r2 + 1]; n2 = thp[r2 + 2];
            b0v = op[r2]; b1v = op[r2 + 1]; b2v = op[r2 + 2];
        }
        float tf[12], af[12];
        *reinterpret_cast<float4*>(&tf[0]) = th0;
        *reinterpret_cast<float4*>(&tf[4]) = th1;
        *reinterpret_cast<float4*>(&tf[8]) = th2v;
        *reinterpret_cast<float4*>(&af[0]) = al0;
        *reinterpret_cast<float4*>(&af[4]) = al1;
        *reinterpret_cast<float4*>(&af[8]) = al2;

        // u0 at column jj+1 = scan position p-1
        float u0n = __shfl_up_sync(FULLMASK, u0p[3], 1);
        if (lane == 0) u0n = NEGC;

        const bool lastrow = (i == 127);
        float c[4], d[4], ud0[4];
#pragma unroll
        for (int k = 0; k < 4; k++) {
            const int q = 3 - k;             // memory slot for this scan index
            float t2k = tf[3 * q + 2];
            float u0 = k ? u0p[k - 1] : u0n;
            ud0[k] = u0;
            c[k] = t2k + lse2(A20 + u0, A21 + u1p[k]);
            d[k] = t2k + A22;
        }
        if (lastrow && lane == 0) { c[0] = tf[11]; d[0] = NEGC; }  // beta(N-1,M-1)=0

        float C = c[0], D = d[0];
#pragma unroll
        for (int k = 1; k < 4; k++) { C = lse2(c[k], d[k] + C); D += d[k]; }
#pragma unroll
        for (int off = 1; off < 32; off <<= 1) {
            float Cu = __shfl_up_sync(FULLMASK, C, off);
            float Du = __shfl_up_sync(FULLMASK, D, off);
            if (lane >= off) { C = lse2(C, D + Cu); D += Du; }
        }
        float Ce = __shfl_up_sync(FULLMASK, C, 1);
        float De = __shfl_up_sync(FULLMASK, D, 1);
        float yin = (lane == 0) ? NEGC : lse2(Ce, De + NEGC);

        float of[12], nu0[4], nu1[4];
#pragma unroll
        for (int k = 0; k < 4; k++) {
            const int q = 3 - k;
            float wr = yin;   // u2 at column jj+1
            float bb0 = lse3(A00 + ud0[k], A01 + u1p[k], A02 + wr);
            float bb1 = lse3(A10 + ud0[k], A11 + u1p[k], A12 + wr);
            float bb2 = lse3(A20 + ud0[k], A21 + u1p[k], A22 + wr);
            if (lastrow && lane == 0 && k == 0) { bb0 = 0.0f; bb1 = 0.0f; bb2 = 0.0f; }
            of[3 * q + 0] = (af[3 * q + 0] + bb0) - logZ;
            of[3 * q + 1] = (af[3 * q + 1] + bb1) - logZ;
            of[3 * q + 2] = (af[3 * q + 2] + bb2) - logZ;
            nu0[k] = bb0 + tf[3 * q + 0];
            nu1[k] = bb1 + tf[3 * q + 1];
            yin = lse2(c[k], d[k] + yin);   // advance u2 chain via scan op
        }

        int wo = i * 96 + fo;
        op[wo]     = *reinterpret_cast<float4*>(&of[0]);
        op[wo + 1] = *reinterpret_cast<float4*>(&of[4]);
        op[wo + 2] = *reinterpret_cast<float4*>(&of[8]);

#pragma unroll
        for (int k = 0; k < 4; k++) { u0p[k] = nu0[k]; u1p[k] = nu1[k]; }
        if (i > 0) { th0 = n0; th1 = n1; th2v = n2; al0 = b0v; al1 = b1v; al2 = b2v; }
    }
}

extern "C" void kernel_launch(void* const* d_in, const int* in_sizes, int n_in,
                              void* d_out, int out_size)
{
    const float* theta = (const float*)d_in[0];
    const float* A     = (const float*)d_in[1];
    float* out         = (float*)d_out;
    int B = in_sizes[1] / 9;   // 256
    fwd_kernel<<<B, 32>>>(theta, A, out);
    bwd_kernel<<<B, 32>>>(theta, A, out);
}